// round 14
// baseline (speedup 1.0000x reference)
#include <cuda_runtime.h>
#include <cstdint>

// ============================================================
// Shaw relative positional embedding:
//   out[b,h,n,r] = (1/8) * sum_d q[b,h,n,d] * E[n-r+2048, d]
// (clip is a no-op: |n-r| <= 2047)
//
// R14: persistent CTAs (grid=148, 512 threads, occ 1) with a
// double-buffered TMA pipeline over 128x128 output tiles:
//   - two full (E band + Q tile) SMEM buffers; fill of tile i+1
//     overlaps permute+MMA of tile i.
//   - 16 compute warps: warp pair (s, s+8) shares a 16-row strip,
//     splits the 18 ni blocks 9/9 (acc 36 regs/thread).
//   - output staged in Bs(p) after MMA; per-row bulk S2G drains
//     during the next tile's MMA (per-thread wait_group 0 gate
//     before that buffer is refilled).
// Math identical to R13 (permuted-B LDS.64, cvt.rna, 1/8 in A):
// rel_err must stay 2.942e-4.
// ============================================================

#define SEQ      2048
#define DHEAD    64
#define NTILES   8192         // 16 x 16 x 32
#define GRID     148
#define TN       128
#define TR       128
#define BAND     256
#define BROW     72           // band row stride (floats): 288B, LDS.64 conflict-free
#define QROW     68           // Q row stride (floats)
#define OROW     132          // staging row stride (floats): 528B = 33*16
#define THREADS  512
#define NI_HALF  9            // ni blocks per warp (half of 18)

#define SMEM_MBAR0  0
#define SMEM_MBAR1  16
#define SMEM_OFF    32
#define BS_BYTES    (BAND * BROW * 4)              // 73728
#define QS_BYTES    (TN * QROW * 4)                // 34816
#define BUF_BYTES   (BS_BYTES + QS_BYTES)          // 108544
#define SMEM_BYTES  (SMEM_OFF + 2 * BUF_BYTES)     // 217120
#define FILL_BYTES  (BAND * DHEAD * 4 + TN * DHEAD * 4)   // 98304

__device__ __forceinline__ uint32_t smem_u32addr(const void* p) {
    uint32_t a;
    asm("{ .reg .u64 t; cvta.to.shared.u64 t, %1; cvt.u32.u64 %0, t; }" : "=r"(a) : "l"(p));
    return a;
}

__device__ __forceinline__ uint32_t f2tf32(float f) {
    uint32_t r;
    asm("cvt.rna.tf32.f32 %0, %1;" : "=r"(r) : "f"(f));
    return r;
}

__device__ __forceinline__ void mma_16x8x8_tf32(float c[4],
                                                const uint32_t a[4],
                                                uint32_t b0, uint32_t b1) {
    asm volatile(
        "mma.sync.aligned.m16n8k8.row.col.f32.tf32.tf32.f32 "
        "{%0,%1,%2,%3}, {%4,%5,%6,%7}, {%8,%9}, {%0,%1,%2,%3};"
        : "+f"(c[0]), "+f"(c[1]), "+f"(c[2]), "+f"(c[3])
        : "r"(a[0]), "r"(a[1]), "r"(a[2]), "r"(a[3]), "r"(b0), "r"(b1));
}

__device__ __forceinline__ void bulk_g2s(uint32_t smem_dst, const void* gmem_src,
                                         uint32_t bytes, uint32_t mbar) {
    uint64_t g;
    asm("cvta.to.global.u64 %0, %1;" : "=l"(g) : "l"(gmem_src));
    asm volatile(
        "cp.async.bulk.shared::cta.global.mbarrier::complete_tx::bytes "
        "[%0], [%1], %2, [%3];"
        :: "r"(smem_dst), "l"(g), "r"(bytes), "r"(mbar) : "memory");
}

__device__ __forceinline__ void bulk_s2g(void* gmem_dst, uint32_t smem_src,
                                         uint32_t bytes) {
    uint64_t g;
    asm("cvta.to.global.u64 %0, %1;" : "=l"(g) : "l"(gmem_dst));
    asm volatile(
        "cp.async.bulk.global.shared::cta.bulk_group [%0], [%1], %2;"
        :: "l"(g), "r"(smem_src), "r"(bytes) : "memory");
}

__device__ __forceinline__ void mbar_wait(uint32_t mbar, uint32_t phase) {
    uint32_t done;
    asm volatile(
        "{\n\t.reg .pred p;\n\t"
        "mbarrier.try_wait.parity.acquire.cta.shared::cta.b64 p, [%1], %2;\n\t"
        "selp.b32 %0, 1, 0, p;\n\t}"
        : "=r"(done) : "r"(mbar), "r"(phase) : "memory");
    if (!done) {
        asm volatile(
            "{\n\t.reg .pred P1;\n\t"
            "WAIT_LOOP_%=:\n\t"
            "mbarrier.try_wait.parity.acquire.cta.shared::cta.b64 P1, [%0], %1, 0x989680;\n\t"
            "@P1 bra.uni WAIT_DONE_%=;\n\t"
            "bra.uni WAIT_LOOP_%=;\n\t"
            "WAIT_DONE_%=:\n\t}"
            :: "r"(mbar), "r"(phase) : "memory");
    }
}

// issue fills for tile T into buffer buf_off (E band + Q tile)
__device__ __forceinline__ void issue_fills(uint32_t sb, uint32_t buf_off, int T,
                                            const float* q, const float* emb,
                                            uint32_t mbar, int tid) {
    const int r0 = (T & 15) << 7;
    const int n0 = ((T >> 4) & 15) << 7;
    const int bz = T >> 8;
    const int j0 = n0 - r0 + 2048 - (TR - 1);
    if (tid < BAND) {
        const float* src = emb + ((size_t)j0 + tid) * DHEAD;
        bulk_g2s(sb + buf_off + (uint32_t)tid * (BROW * 4), src, DHEAD * 4, mbar);
    } else if (tid < BAND + TN) {
        const int row = tid - BAND;
        const float* src = q + ((size_t)bz * SEQ + n0 + row) * DHEAD;
        bulk_g2s(sb + buf_off + BS_BYTES + (uint32_t)row * (QROW * 4), src,
                 DHEAD * 4, mbar);
    }
}

__global__ void __launch_bounds__(THREADS, 1)
shaw_relpos_kernel(const float* __restrict__ q,
                   const float* __restrict__ emb,
                   float* __restrict__ out)
{
    extern __shared__ char smem_raw[];
    const uint32_t sb = smem_u32addr(smem_raw);

    const int tid  = threadIdx.x;
    const int w    = tid >> 5;
    const int lane = tid & 31;
    const int gid  = lane >> 2;               // 0..7
    const int t    = lane & 3;                // 0..3
    const int s    = w & 7;                   // 16-row strip id
    const int h    = w >> 3;                  // ni half (0/1)

    // ---- init mbarriers, prologue fill of buffer 0 ----
    if (tid == 0) {
        asm volatile("mbarrier.init.shared.b64 [%0], %1;" :: "r"(sb + SMEM_MBAR0), "r"(1) : "memory");
        asm volatile("mbarrier.init.shared.b64 [%0], %1;" :: "r"(sb + SMEM_MBAR1), "r"(1) : "memory");
    }
    __syncthreads();
    if (tid == 0) {
        asm volatile("mbarrier.arrive.expect_tx.shared.b64 _, [%0], %1;"
                     :: "r"(sb + SMEM_MBAR0), "r"((uint32_t)FILL_BYTES) : "memory");
    }
    __syncthreads();
    issue_fills(sb, SMEM_OFF, blockIdx.x, q, emb, sb + SMEM_MBAR0, tid);

    uint32_t phase[2] = {0u, 0u};
    int p = 0;

    for (int T = blockIdx.x; T < NTILES; T += GRID, p ^= 1) {
        const uint32_t buf  = SMEM_OFF + (uint32_t)p * BUF_BYTES;
        const uint32_t mb   = sb + (p ? SMEM_MBAR1 : SMEM_MBAR0);
        uint32_t* Bs = (uint32_t*)(smem_raw + buf);              // [BAND][BROW]
        float*    Qs = (float*)(smem_raw + buf + BS_BYTES);      // [TN][QROW]
        float*  outs = (float*)(smem_raw + buf);                 // staging aliases Bs

        // ---- wait fill of this buffer ----
        mbar_wait(mb, phase[p]);
        phase[p] ^= 1;

        // ---- in-place permute + tf32-convert band: dst[2t+u]=tf32(src[t+4u]) ----
        #pragma unroll
        for (int i = 0; i < 4; i++) {
            const int idx = i * THREADS + tid;        // 2048 8-word groups
            const int row = idx >> 3, kg = idx & 7;
            uint32_t* g = &Bs[row * BROW + kg * 8];
            float4 s0 = *(float4*)g;
            float4 s1 = *(float4*)(g + 4);
            uint4 d0 = make_uint4(f2tf32(s0.x), f2tf32(s1.x), f2tf32(s0.y), f2tf32(s1.y));
            uint4 d1 = make_uint4(f2tf32(s0.z), f2tf32(s1.z), f2tf32(s0.w), f2tf32(s1.w));
            *(uint4*)g       = d0;
            *(uint4*)(g + 4) = d1;
        }
        __syncthreads();

        // ---- prefetch next tile into the other buffer ----
        const int Tn = T + GRID;
        if (Tn < NTILES) {
            // s2g group reading the other buffer's staging (tile T-GRID) must
            // be fully drained before refill. Each s2g thread waits only its
            // own groups (<=1 outstanding, issued one full tile ago).
            if (tid < TN) {
                asm volatile("cp.async.bulk.wait_group 0;" ::: "memory");
            }
            if (tid == 0) {
                asm volatile("mbarrier.arrive.expect_tx.shared.b64 _, [%0], %1;"
                             :: "r"(sb + (p ? SMEM_MBAR0 : SMEM_MBAR1)),
                                "r"((uint32_t)FILL_BYTES) : "memory");
            }
            asm volatile("fence.proxy.async.shared::cta;" ::: "memory");
            __syncthreads();
            issue_fills(sb, SMEM_OFF + (uint32_t)(p ^ 1) * BUF_BYTES, Tn,
                        q, emb, sb + (p ? SMEM_MBAR0 : SMEM_MBAR1), tid);
        }

        // ---- A fragments (strip s: rows 16s..16s+15), cvt.rna, 1/8 folded ----
        uint32_t a[8][4];
        {
            const float* q_lo = &Qs[(s * 16 + gid) * QROW];
            const float* q_hi = q_lo + 8 * QROW;
            #pragma unroll
            for (int k = 0; k < 8; k++) {
                const int c0 = k * 8 + t;
                a[k][0] = f2tf32(0.125f * q_lo[c0]);
                a[k][1] = f2tf32(0.125f * q_hi[c0]);
                a[k][2] = f2tf32(0.125f * q_lo[c0 + 4]);
                a[k][3] = f2tf32(0.125f * q_hi[c0 + 4]);
            }
        }

        // ---- MMA: this warp's 9 ni blocks (half of strip's 18) ----
        float acc[NI_HALF][4];
        {
            const int ni_lo = 2 * s + h * NI_HALF;
            #pragma unroll
            for (int nn = 0; nn < NI_HALF; nn++) {
                acc[nn][0] = acc[nn][1] = acc[nn][2] = acc[nn][3] = 0.f;
                const uint32_t* brow = &Bs[((ni_lo + nn) * 8 + gid) * BROW + 2 * t];
                #pragma unroll
                for (int k = 0; k < 8; k++) {
                    uint2 b = *(const uint2*)&brow[8 * k];
                    mma_16x8x8_tf32(acc[nn], a[k], b.x, b.y);
                }
            }
        }
        __syncthreads();   // all warps done reading Bs before staging overwrite

        // ---- scatter into staging (diag extraction, bijective) ----
        {
            const int ni_lo = 2 * s + h * NI_HALF;
            const int nlo = s * 16 + gid;
            float* s_lo = outs + (size_t)nlo * OROW;
            float* s_hi = s_lo + (size_t)8 * OROW;
            #pragma unroll
            for (int nn = 0; nn < NI_HALF; nn++) {
                const int cc  = (ni_lo + nn) * 8 + t * 2;
                const int rl0 = nlo + 127 - cc;
                const int rl2 = rl0 + 8;
                if ((unsigned)rl0 < TR)       s_lo[rl0]     = acc[nn][0];
                if ((unsigned)(rl0 - 1) < TR) s_lo[rl0 - 1] = acc[nn][1];
                if ((unsigned)rl2 < TR)       s_hi[rl2]     = acc[nn][2];
                if ((unsigned)(rl2 - 1) < TR) s_hi[rl2 - 1] = acc[nn][3];
            }
        }
        __syncthreads();
        asm volatile("fence.proxy.async.shared::cta;" ::: "memory");

        // ---- per-row bulk store: staging -> gmem (512 B rows) ----
        if (tid < TN) {
            const int r0 = (T & 15) << 7;
            const int n0 = ((T >> 4) & 15) << 7;
            const int bz = T >> 8;
            float* dst = out + ((size_t)bz * SEQ + n0 + tid) * SEQ + r0;
            bulk_s2g(dst, sb + buf + (uint32_t)tid * (OROW * 4), TR * 4);
            asm volatile("cp.async.bulk.commit_group;" ::: "memory");
        }
    }

    if (tid < TN) {
        asm volatile("cp.async.bulk.wait_group 0;" ::: "memory");
    }
}

// ---------------- launch ----------------

extern "C" void kernel_launch(void* const* d_in, const int* in_sizes, int n_in,
                              void* d_out, int out_size) {
    // metadata order: q [2,16,2048,64], k (unused), rel_pos_emb [4097,64]
    const float* q   = (const float*)d_in[0];
    const float* emb = (const float*)d_in[2];
    for (int i = 0; i < n_in; i++) {
        if (in_sizes[i] == 4097 * 64) emb = (const float*)d_in[i];
    }
    float* out = (float*)d_out;

    cudaFuncSetAttribute(shaw_relpos_kernel,
                         cudaFuncAttributeMaxDynamicSharedMemorySize, SMEM_BYTES);

    shaw_relpos_kernel<<<GRID, THREADS, SMEM_BYTES>>>(q, emb, out);
}

// round 15
// speedup vs baseline: 1.0899x; 1.0899x over previous
#include <cuda_runtime.h>
#include <cstdint>

// ============================================================
// Shaw relative positional embedding:
//   out[b,h,n,r] = (1/8) * sum_d q[b,h,n,d] * E[n-r+2048, d]
// (clip is a no-op: |n-r| <= 2047)
//
// Per 128x128 output tile, banded GEMM with mma.sync m16n8k8 tf32.
// Base = R11 (217.5us, best). R15 single change: the monolithic
// fill mbarrier is split into 1 Q barrier + 8 per-chunk E barriers
// (32 band rows each). A-prep waits only on Q; the MMA loop waits
// on E chunk (ni>>2) immediately before first use. Warps start
// computing after ~8KB instead of 96KB, staggered.
// Math identical to R11: rel_err must stay 2.942e-4.
// ============================================================

#define SEQ      2048
#define DHEAD    64
#define BH       32
#define TN       128
#define TR       128
#define BAND     256          // band rows staged
#define BROW     68           // band SMEM row stride (floats): 272B, conflict-free
#define QROW     68           // Q SMEM row stride (floats)
#define OROW     132          // staging row stride (floats): 528B = 33*16
#define THREADS  256
#define NI_PER_W 18           // n8 blocks per warp (band coverage)

// SMEM: [0,8) Q mbar; [8,72) 8 E chunk mbars; [128,+Bs) band; then Qs.
// Epilogue staging aliases Bs.
#define SMEM_QBAR   0
#define SMEM_EBAR   8
#define SMEM_OFF    128
#define BS_BYTES    (BAND * BROW * 4)              // 69632
#define QS_BYTES    (TN * QROW * 4)                // 34816
#define SMEM_BYTES  (SMEM_OFF + BS_BYTES + QS_BYTES)   // 104576 (occ 2)

__device__ __forceinline__ uint32_t smem_u32addr(const void* p) {
    uint32_t a;
    asm("{ .reg .u64 t; cvta.to.shared.u64 t, %1; cvt.u32.u64 %0, t; }" : "=r"(a) : "l"(p));
    return a;
}

__device__ __forceinline__ uint32_t f2tf32(float f) {
    uint32_t r;
    asm("cvt.rna.tf32.f32 %0, %1;" : "=r"(r) : "f"(f));
    return r;
}

__device__ __forceinline__ void mma_16x8x8_tf32(float c[4],
                                                const uint32_t a[4],
                                                uint32_t b0, uint32_t b1) {
    asm volatile(
        "mma.sync.aligned.m16n8k8.row.col.f32.tf32.tf32.f32 "
        "{%0,%1,%2,%3}, {%4,%5,%6,%7}, {%8,%9}, {%0,%1,%2,%3};"
        : "+f"(c[0]), "+f"(c[1]), "+f"(c[2]), "+f"(c[3])
        : "r"(a[0]), "r"(a[1]), "r"(a[2]), "r"(a[3]), "r"(b0), "r"(b1));
}

__device__ __forceinline__ void bulk_g2s(uint32_t smem_dst, const void* gmem_src,
                                         uint32_t bytes, uint32_t mbar) {
    uint64_t g;
    asm("cvta.to.global.u64 %0, %1;" : "=l"(g) : "l"(gmem_src));
    asm volatile(
        "cp.async.bulk.shared::cta.global.mbarrier::complete_tx::bytes "
        "[%0], [%1], %2, [%3];"
        :: "r"(smem_dst), "l"(g), "r"(bytes), "r"(mbar) : "memory");
}

__device__ __forceinline__ void bulk_s2g(void* gmem_dst, uint32_t smem_src,
                                         uint32_t bytes) {
    uint64_t g;
    asm("cvta.to.global.u64 %0, %1;" : "=l"(g) : "l"(gmem_dst));
    asm volatile(
        "cp.async.bulk.global.shared::cta.bulk_group [%0], [%1], %2;"
        :: "l"(g), "r"(smem_src), "r"(bytes) : "memory");
}

__device__ __forceinline__ void mbar_wait0(uint32_t mbar) {
    uint32_t done;
    asm volatile(
        "{\n\t.reg .pred p;\n\t"
        "mbarrier.try_wait.parity.acquire.cta.shared::cta.b64 p, [%1], 0;\n\t"
        "selp.b32 %0, 1, 0, p;\n\t}"
        : "=r"(done) : "r"(mbar) : "memory");
    if (!done) {
        asm volatile(
            "{\n\t.reg .pred P1;\n\t"
            "WAIT_LOOP_%=:\n\t"
            "mbarrier.try_wait.parity.acquire.cta.shared::cta.b64 P1, [%0], 0, 0x989680;\n\t"
            "@P1 bra.uni WAIT_DONE_%=;\n\t"
            "bra.uni WAIT_LOOP_%=;\n\t"
            "WAIT_DONE_%=:\n\t}"
            :: "r"(mbar) : "memory");
    }
}

__global__ void __launch_bounds__(THREADS, 2)
shaw_relpos_kernel(const float* __restrict__ q,
                   const float* __restrict__ emb,
                   float* __restrict__ out)
{
    extern __shared__ char smem_raw[];
    const uint32_t sb = smem_u32addr(smem_raw);

    float* Bs    = (float*)(smem_raw + SMEM_OFF);              // [BAND][BROW] raw f32
    float* Qs    = (float*)(smem_raw + SMEM_OFF + BS_BYTES);   // [TN][QROW] raw f32
    float* outs  = (float*)(smem_raw + SMEM_OFF);              // staging (aliases Bs)

    const int tid  = threadIdx.x;
    const int w    = tid >> 5;                // warp id = 16-row block
    const int lane = tid & 31;
    const int gid  = lane >> 2;               // 0..7
    const int t    = lane & 3;                // 0..3

    const int n0 = blockIdx.y * TN;
    const int r0 = blockIdx.x * TR;
    const int bz = blockIdx.z;                       // b*16 + h
    const int j0 = n0 - r0 + 2048 - (TR - 1);        // band start row in E, [1, 3841]

    // ---- mbarrier init: Q (128 arrives), 8 E chunks (32 arrives each) ----
    if (tid == 0) {
        asm volatile("mbarrier.init.shared.b64 [%0], %1;"
                     :: "r"(sb + SMEM_QBAR), "r"(TN) : "memory");
        #pragma unroll
        for (int c = 0; c < 8; c++) {
            asm volatile("mbarrier.init.shared.b64 [%0], %1;"
                         :: "r"(sb + SMEM_EBAR + c * 8), "r"(32) : "memory");
        }
    }
    __syncthreads();

    // ---- async fills ----
    // Q tile: 128 rows x 256 B (Q barrier; issue first)
    if (tid < TN) {
        asm volatile("mbarrier.arrive.expect_tx.shared.b64 _, [%0], %1;"
                     :: "r"(sb + SMEM_QBAR), "r"((uint32_t)(DHEAD * 4)) : "memory");
        const float* src = q + ((size_t)bz * SEQ + n0 + tid) * DHEAD;
        bulk_g2s(sb + SMEM_OFF + BS_BYTES + (uint32_t)tid * (QROW * 4), src,
                 DHEAD * 4, sb + SMEM_QBAR);
    }
    // E band: 256 rows x 256 B; row tid -> chunk (tid >> 5)
    {
        const uint32_t embar = sb + SMEM_EBAR + (uint32_t)(tid >> 5) * 8;
        asm volatile("mbarrier.arrive.expect_tx.shared.b64 _, [%0], %1;"
                     :: "r"(embar), "r"((uint32_t)(DHEAD * 4)) : "memory");
        const float* src = emb + ((size_t)j0 + tid) * DHEAD;
        bulk_g2s(sb + SMEM_OFF + (uint32_t)tid * (BROW * 4), src, DHEAD * 4, embar);
    }

    // ---- Q ready: A fragments (16 rows x K=64), cvt.rna, 1/8 folded ----
    // m16n8k8 tf32 A: a0:(gid, 8k+t) a1:(gid+8, 8k+t) a2:(gid, 8k+t+4) a3:(gid+8, 8k+t+4)
    mbar_wait0(sb + SMEM_QBAR);
    uint32_t a[8][4];
    {
        const float* q_lo = &Qs[(w * 16 + gid) * QROW];
        const float* q_hi = q_lo + 8 * QROW;
        #pragma unroll
        for (int k = 0; k < 8; k++) {
            const int c0 = k * 8 + t;
            a[k][0] = f2tf32(0.125f * q_lo[c0]);
            a[k][1] = f2tf32(0.125f * q_hi[c0]);
            a[k][2] = f2tf32(0.125f * q_lo[c0 + 4]);
            a[k][3] = f2tf32(0.125f * q_hi[c0 + 4]);
        }
    }

    // ---- Band-restricted MMA with progressive per-chunk E waits ----
    float acc[NI_PER_W][4];
    {
        const int ni_lo = 2 * w;
        int c_have = -1;
        #pragma unroll
        for (int nn = 0; nn < NI_PER_W; nn++) {
            const int ni = ni_lo + nn;
            const int c  = ni >> 2;            // 32-row chunk of band rows [8ni, 8ni+8)
            if (c != c_have) {                 // monotone non-decreasing
                mbar_wait0(sb + SMEM_EBAR + (uint32_t)c * 8);
                c_have = c;
            }
            acc[nn][0] = acc[nn][1] = acc[nn][2] = acc[nn][3] = 0.f;
            const float* brow = &Bs[(ni * 8 + gid) * BROW];
            #pragma unroll
            for (int k = 0; k < 8; k++) {
                uint32_t b0 = f2tf32(brow[k * 8 + t]);
                uint32_t b1 = f2tf32(brow[k * 8 + t + 4]);
                mma_16x8x8_tf32(acc[nn], a[k], b0, b1);
            }
        }
    }
    __syncthreads();   // all warps done reading Bs before staging overwrite

    // ---- Scatter accumulators into SMEM staging (diag extraction) ----
    // C frag: c0:(gid, cc) c1:(gid, cc+1) c2:(gid+8, cc) c3:(gid+8, cc+1), cc = ni*8+2t
    // rl = nl + 127 - col; bijective onto the 128x128 tile. Scale already in A.
    {
        const int ni_lo = 2 * w;
        const int nlo = w * 16 + gid;       // rows nlo and nlo+8
        float* s_lo = outs + (size_t)nlo * OROW;
        float* s_hi = s_lo + (size_t)8 * OROW;
        #pragma unroll
        for (int nn = 0; nn < NI_PER_W; nn++) {
            const int cc  = (ni_lo + nn) * 8 + t * 2;
            const int rl0 = nlo + 127 - cc;          // row nlo,   col cc
            const int rl2 = rl0 + 8;                 // row nlo+8, col cc
            if ((unsigned)rl0 < TR)       s_lo[rl0]     = acc[nn][0];
            if ((unsigned)(rl0 - 1) < TR) s_lo[rl0 - 1] = acc[nn][1];
            if ((unsigned)rl2 < TR)       s_hi[rl2]     = acc[nn][2];
            if ((unsigned)(rl2 - 1) < TR) s_hi[rl2 - 1] = acc[nn][3];
        }
    }
    __syncthreads();
    asm volatile("fence.proxy.async.shared::cta;" ::: "memory");

    // ---- Per-row TMA bulk store: staging -> gmem (512 B rows) ----
    if (tid < TN) {
        float* dst = out + ((size_t)bz * SEQ + n0 + tid) * SEQ + r0;
        bulk_s2g(dst, sb + SMEM_OFF + (uint32_t)tid * (OROW * 4), TR * 4);
    }
    asm volatile("cp.async.bulk.commit_group;" ::: "memory");
    asm volatile("cp.async.bulk.wait_group 0;" ::: "memory");
}

// ---------------- launch ----------------

extern "C" void kernel_launch(void* const* d_in, const int* in_sizes, int n_in,
                              void* d_out, int out_size) {
    // metadata order: q [2,16,2048,64], k (unused), rel_pos_emb [4097,64]
    const float* q   = (const float*)d_in[0];
    const float* emb = (const float*)d_in[2];
    for (int i = 0; i < n_in; i++) {
        if (in_sizes[i] == 4097 * 64) emb = (const float*)d_in[i];
    }
    float* out = (float*)d_out;

    cudaFuncSetAttribute(shaw_relpos_kernel,
                         cudaFuncAttributeMaxDynamicSharedMemorySize, SMEM_BYTES);

    dim3 grid(SEQ / TR, SEQ / TN, BH);   // 16 x 16 x 32 = 8192 CTAs
    shaw_relpos_kernel<<<grid, THREADS, SMEM_BYTES>>>(q, emb, out);
}

// round 16
// speedup vs baseline: 1.1068x; 1.0155x over previous
#include <cuda_runtime.h>
#include <cstdint>

// ============================================================
// Shaw relative positional embedding:
//   out[b,h,n,r] = (1/8) * sum_d q[b,h,n,d] * E[n-r+2048, d]
// (clip is a no-op: |n-r| <= 2047)
//
// Banded GEMM with mma.sync m16n8k8 tf32.
// R16: tile shrunk 128x128 -> 64x128 to break the occupancy cap:
//   SMEM/CTA 104.5KB -> 69.8KB  => 3 CTAs/SM
//   acc regs 72 -> 36 (warp-pair splits a strip's 18 ni blocks)
//   __launch_bounds__(256,3)    => <=85 regs
// 24 warps/SM (was 16): more latency hiding for the LDS->cvt->MMA
// chains that have kept issue ~50% / tensor ~28% since R11.
// Math identical to R11: rel_err must stay 2.942e-4.
// ============================================================

#define SEQ      2048
#define DHEAD    64
#define TN       64           // n rows per tile
#define TR       128          // r cols per tile
#define BAND     192          // band rows staged (191 used)
#define BROW     68           // band SMEM row stride (floats): 272B, conflict-free
#define QROW     68           // Q SMEM row stride (floats)
#define OROW     132          // staging row stride (floats): 528B = 33*16
#define THREADS  256
#define NI_HALF  9            // ni blocks per warp (half of a strip's 18)

// SMEM: [0,16) mbarrier; [128,+Bs) band; then Qs. Staging aliases Bs.
#define SMEM_MBAR   0
#define SMEM_OFF    128
#define BS_BYTES    (BAND * BROW * 4)              // 52224
#define QS_BYTES    (TN * QROW * 4)                // 17408
#define SMEM_BYTES  (SMEM_OFF + BS_BYTES + QS_BYTES)   // 69760  (3 CTAs/SM)
#define FILL_BYTES  (BAND * DHEAD * 4 + TN * DHEAD * 4)   // 65536

__device__ __forceinline__ uint32_t smem_u32addr(const void* p) {
    uint32_t a;
    asm("{ .reg .u64 t; cvta.to.shared.u64 t, %1; cvt.u32.u64 %0, t; }" : "=r"(a) : "l"(p));
    return a;
}

__device__ __forceinline__ uint32_t f2tf32(float f) {
    uint32_t r;
    asm("cvt.rna.tf32.f32 %0, %1;" : "=r"(r) : "f"(f));
    return r;
}

__device__ __forceinline__ void mma_16x8x8_tf32(float c[4],
                                                const uint32_t a[4],
                                                uint32_t b0, uint32_t b1) {
    asm volatile(
        "mma.sync.aligned.m16n8k8.row.col.f32.tf32.tf32.f32 "
        "{%0,%1,%2,%3}, {%4,%5,%6,%7}, {%8,%9}, {%0,%1,%2,%3};"
        : "+f"(c[0]), "+f"(c[1]), "+f"(c[2]), "+f"(c[3])
        : "r"(a[0]), "r"(a[1]), "r"(a[2]), "r"(a[3]), "r"(b0), "r"(b1));
}

__device__ __forceinline__ void bulk_g2s(uint32_t smem_dst, const void* gmem_src,
                                         uint32_t bytes, uint32_t mbar) {
    uint64_t g;
    asm("cvta.to.global.u64 %0, %1;" : "=l"(g) : "l"(gmem_src));
    asm volatile(
        "cp.async.bulk.shared::cta.global.mbarrier::complete_tx::bytes "
        "[%0], [%1], %2, [%3];"
        :: "r"(smem_dst), "l"(g), "r"(bytes), "r"(mbar) : "memory");
}

__device__ __forceinline__ void bulk_s2g(void* gmem_dst, uint32_t smem_src,
                                         uint32_t bytes) {
    uint64_t g;
    asm("cvta.to.global.u64 %0, %1;" : "=l"(g) : "l"(gmem_dst));
    asm volatile(
        "cp.async.bulk.global.shared::cta.bulk_group [%0], [%1], %2;"
        :: "l"(g), "r"(smem_src), "r"(bytes) : "memory");
}

__global__ void __launch_bounds__(THREADS, 3)
shaw_relpos_kernel(const float* __restrict__ q,
                   const float* __restrict__ emb,
                   float* __restrict__ out)
{
    extern __shared__ char smem_raw[];
    const uint32_t sb = smem_u32addr(smem_raw);
    const uint32_t mbar = sb + SMEM_MBAR;

    float* Bs   = (float*)(smem_raw + SMEM_OFF);              // [BAND][BROW] raw f32
    float* Qs   = (float*)(smem_raw + SMEM_OFF + BS_BYTES);   // [TN][QROW] raw f32
    float* outs = (float*)(smem_raw + SMEM_OFF);              // staging (aliases Bs)

    const int tid  = threadIdx.x;
    const int w    = tid >> 5;
    const int lane = tid & 31;
    const int gid  = lane >> 2;               // 0..7
    const int t    = lane & 3;                // 0..3
    const int s    = w & 3;                   // 16-row strip id (4 strips)
    const int h    = w >> 2;                  // ni half (0/1)

    const int n0 = blockIdx.y * TN;
    const int r0 = blockIdx.x * TR;
    const int bz = blockIdx.z;                       // b*16 + h
    const int j0 = n0 - r0 + 2048 - (TR - 1);        // band start row in E, [1, 3905]

    // ---- mbarrier init, then async fills ----
    if (tid == 0) {
        asm volatile("mbarrier.init.shared.b64 [%0], %1;" :: "r"(mbar), "r"(1) : "memory");
    }
    __syncthreads();
    if (tid == 0) {
        asm volatile("mbarrier.arrive.expect_tx.shared.b64 _, [%0], %1;"
                     :: "r"(mbar), "r"((uint32_t)FILL_BYTES) : "memory");
    }
    // E band: 192 rows x 256 B (threads 0..191)
    if (tid < BAND) {
        const float* src = emb + ((size_t)j0 + tid) * DHEAD;
        bulk_g2s(sb + SMEM_OFF + (uint32_t)tid * (BROW * 4), src, DHEAD * 4, mbar);
    } else if (tid < BAND + TN) {
        // Q tile: 64 rows x 256 B (threads 192..255)
        const int row = tid - BAND;
        const float* src = q + ((size_t)bz * SEQ + n0 + row) * DHEAD;
        bulk_g2s(sb + SMEM_OFF + BS_BYTES + (uint32_t)row * (QROW * 4), src,
                 DHEAD * 4, mbar);
    }
    // wait (parity 0)
    {
        uint32_t done;
        asm volatile(
            "{\n\t.reg .pred p;\n\t"
            "mbarrier.try_wait.parity.acquire.cta.shared::cta.b64 p, [%1], 0;\n\t"
            "selp.b32 %0, 1, 0, p;\n\t}"
            : "=r"(done) : "r"(mbar) : "memory");
        if (!done) {
            asm volatile(
                "{\n\t.reg .pred P1;\n\t"
                "WAIT_LOOP_%=:\n\t"
                "mbarrier.try_wait.parity.acquire.cta.shared::cta.b64 P1, [%0], 0, 0x989680;\n\t"
                "@P1 bra.uni WAIT_DONE_%=;\n\t"
                "bra.uni WAIT_LOOP_%=;\n\t"
                "WAIT_DONE_%=:\n\t}"
                :: "r"(mbar) : "memory");
        }
    }

    // ---- A fragments (strip s: 16 rows x K=64), cvt.rna, 1/8 folded ----
    // m16n8k8 tf32 A: a0:(gid, 8k+t) a1:(gid+8, 8k+t) a2:(gid, 8k+t+4) a3:(gid+8, 8k+t+4)
    uint32_t a[8][4];
    {
        const float* q_lo = &Qs[(s * 16 + gid) * QROW];
        const float* q_hi = q_lo + 8 * QROW;
        #pragma unroll
        for (int k = 0; k < 8; k++) {
            const int c0 = k * 8 + t;
            a[k][0] = f2tf32(0.125f * q_lo[c0]);
            a[k][1] = f2tf32(0.125f * q_hi[c0]);
            a[k][2] = f2tf32(0.125f * q_lo[c0 + 4]);
            a[k][3] = f2tf32(0.125f * q_hi[c0 + 4]);
        }
    }

    // ---- Band-restricted MMA: this warp's 9 ni blocks (half of strip's 18) ----
    float acc[NI_HALF][4];
    {
        const int ni_lo = 2 * s + h * NI_HALF;
        #pragma unroll
        for (int nn = 0; nn < NI_HALF; nn++) {
            acc[nn][0] = acc[nn][1] = acc[nn][2] = acc[nn][3] = 0.f;
            const float* brow = &Bs[((ni_lo + nn) * 8 + gid) * BROW];
            #pragma unroll
            for (int k = 0; k < 8; k++) {
                uint32_t b0 = f2tf32(brow[k * 8 + t]);
                uint32_t b1 = f2tf32(brow[k * 8 + t + 4]);
                mma_16x8x8_tf32(acc[nn], a[k], b0, b1);
            }
        }
    }
    __syncthreads();   // all warps done reading Bs before staging overwrite

    // ---- Scatter accumulators into SMEM staging (diag extraction) ----
    // C frag: c0:(gid, cc) c1:(gid, cc+1) c2:(gid+8, cc) c3:(gid+8, cc+1), cc = ni*8+2t
    // rl = nl + 127 - cc; bijective onto the 64x128 tile. Scale already in A.
    {
        const int ni_lo = 2 * s + h * NI_HALF;
        const int nlo = s * 16 + gid;       // rows nlo and nlo+8
        float* s_lo = outs + (size_t)nlo * OROW;
        float* s_hi = s_lo + (size_t)8 * OROW;
        #pragma unroll
        for (int nn = 0; nn < NI_HALF; nn++) {
            const int cc  = (ni_lo + nn) * 8 + t * 2;
            const int rl0 = nlo + (TR - 1) - cc;     // row nlo,   col cc
            const int rl2 = rl0 + 8;                 // row nlo+8, col cc
            if ((unsigned)rl0 < TR)       s_lo[rl0]     = acc[nn][0];
            if ((unsigned)(rl0 - 1) < TR) s_lo[rl0 - 1] = acc[nn][1];
            if ((unsigned)rl2 < TR)       s_hi[rl2]     = acc[nn][2];
            if ((unsigned)(rl2 - 1) < TR) s_hi[rl2 - 1] = acc[nn][3];
        }
    }
    __syncthreads();
    asm volatile("fence.proxy.async.shared::cta;" ::: "memory");

    // ---- Per-row TMA bulk store: staging -> gmem (512 B rows) ----
    if (tid < TN) {
        float* dst = out + ((size_t)bz * SEQ + n0 + tid) * SEQ + r0;
        bulk_s2g(dst, sb + SMEM_OFF + (uint32_t)tid * (OROW * 4), TR * 4);
    }
    asm volatile("cp.async.bulk.commit_group;" ::: "memory");
    asm volatile("cp.async.bulk.wait_group 0;" ::: "memory");
}

// ---------------- launch ----------------

extern "C" void kernel_launch(void* const* d_in, const int* in_sizes, int n_in,
                              void* d_out, int out_size) {
    // metadata order: q [2,16,2048,64], k (unused), rel_pos_emb [4097,64]
    const float* q   = (const float*)d_in[0];
    const float* emb = (const float*)d_in[2];
    for (int i = 0; i < n_in; i++) {
        if (in_sizes[i] == 4097 * 64) emb = (const float*)d_in[i];
    }
    float* out = (float*)d_out;

    cudaFuncSetAttribute(shaw_relpos_kernel,
                         cudaFuncAttributeMaxDynamicSharedMemorySize, SMEM_BYTES);

    dim3 grid(SEQ / TR, SEQ / TN, 32);   // 16 x 32 x 32 = 16384 CTAs
    shaw_relpos_kernel<<<grid, THREADS, SMEM_BYTES>>>(q, emb, out);
}